// round 1
// baseline (speedup 1.0000x reference)
#include <cuda_runtime.h>
#include <math_constants.h>

// Tropical (max-plus) depthwise 5x5 conv, stride=1, pad=2, dil=1.
// x: (8,32,224,224) f32, kernel: (32,1,5,5) f32, out: (8,32,224,224) f32.
// out[b,c,y,x] = max_{i,j in 0..4} x[b,c, y+i-2, x+j-2] + kernel[c,0,4-i,4-j]
// (out-of-range input treated as -inf)

#define TILE 32
#define HALO 2
#define SW (TILE + 2 * HALO) // 36

static constexpr int Hdim = 224;
static constexpr int Wdim = 224;
static constexpr int Cdim = 32;
static constexpr int Bdim = 8;

__global__ __launch_bounds__(256, 6)
void tropical_conv_kernel(const float* __restrict__ x,
                          const float* __restrict__ kern,
                          float* __restrict__ out) {
    __shared__ float sm[SW * SW];
    __shared__ float wsm[25];

    const int tid = threadIdx.x;
    const int bc  = blockIdx.z;          // b*32 + c
    const int c   = bc & 31;
    const int gx0 = blockIdx.x * TILE;
    const int gy0 = blockIdx.y * TILE;

    const float* __restrict__ xp = x + (size_t)bc * (Hdim * Wdim);

    // flipped weights: wsm[i*5+j] = kernel[c, 0, 4-i, 4-j]
    if (tid < 25) wsm[tid] = kern[c * 25 + (24 - tid)];

    // Cooperative tile load: 36x36 input window (with -inf halo padding).
    #pragma unroll
    for (int base = 0; base < SW * SW; base += 256) {
        int idx = base + tid;
        if (idx < SW * SW) {
            int r = idx / SW;
            int q = idx - r * SW;
            int gy  = gy0 + r - HALO;
            int gxx = gx0 + q - HALO;
            float v = -CUDART_INF_F;
            if ((unsigned)gy < (unsigned)Hdim && (unsigned)gxx < (unsigned)Wdim)
                v = xp[gy * Wdim + gxx];
            sm[idx] = v;
        }
    }
    __syncthreads();

    // Hoist weights to registers (broadcast LDS, conflict-free).
    float w[25];
    #pragma unroll
    for (int i = 0; i < 25; i++) w[i] = wsm[i];

    const int tx  = tid & 31;        // output column within tile
    const int oy0 = (tid >> 5) * 4;  // first of 4 vertical outputs

    float acc[4];
    #pragma unroll
    for (int k = 0; k < 4; k++) acc[k] = -CUDART_INF_F;

    // Stream 8 input rows; each row feeds up to 4 of the accumulators.
    #pragma unroll
    for (int r = 0; r < 8; r++) {
        float xv[5];
        #pragma unroll
        for (int j = 0; j < 5; j++)
            xv[j] = sm[(oy0 + r) * SW + tx + j];

        #pragma unroll
        for (int k = 0; k < 4; k++) {
            const int i = r - k;  // weight row
            if (i >= 0 && i < 5) {
                #pragma unroll
                for (int j = 0; j < 5; j++)
                    acc[k] = fmaxf(acc[k], xv[j] + w[i * 5 + j]);
            }
        }
    }

    float* __restrict__ op = out + (size_t)bc * (Hdim * Wdim);
    #pragma unroll
    for (int k = 0; k < 4; k++)
        op[(gy0 + oy0 + k) * Wdim + gx0 + tx] = acc[k];
}

extern "C" void kernel_launch(void* const* d_in, const int* in_sizes, int n_in,
                              void* d_out, int out_size) {
    const float* x    = (const float*)d_in[0];
    const float* kern = (const float*)d_in[1];
    float* out = (float*)d_out;

    dim3 grid(Wdim / TILE, Hdim / TILE, Bdim * Cdim);  // (7, 7, 256)
    tropical_conv_kernel<<<grid, 256>>>(x, kern, out);
}

// round 2
// speedup vs baseline: 1.0589x; 1.0589x over previous
#include <cuda_runtime.h>
#include <math_constants.h>

// Tropical (max-plus) depthwise 5x5 conv, stride=1, pad=2, dil=1.
// x: (8,32,224,224) f32, kernel: (32,1,5,5) f32, out: (8,32,224,224) f32.
// out[b,c,y,x] = max_{i,j} x[b,c, y+i-2, x+j-2] + kernel[c,0,4-i,4-j]
//
// R2: issue/alu-bound per ncu (issue 80.5%, alu 55%). Cut overhead inst:
//  - 1x4 horizontal outputs per thread, inputs via 2x LDS.128 per row
//  - STG.128 output store
//  - acc init from first tap (no -inf FMNMX)

#define TILE 32
#define HALO 2
#define SW (TILE + 2 * HALO) // 36 floats per shared row (144B, 16B-aligned)

static constexpr int Hdim = 224;
static constexpr int Wdim = 224;
static constexpr int Cdim = 32;
static constexpr int Bdim = 8;

__global__ __launch_bounds__(256)
void tropical_conv_kernel(const float* __restrict__ x,
                          const float* __restrict__ kern,
                          float* __restrict__ out) {
    __shared__ __align__(16) float sm[SW * SW];
    __shared__ float wsm[25];

    const int tid = threadIdx.x;
    const int bc  = blockIdx.z;          // b*32 + c
    const int c   = bc & 31;
    const int gx0 = blockIdx.x * TILE;
    const int gy0 = blockIdx.y * TILE;

    const float* __restrict__ xp = x + (size_t)bc * (Hdim * Wdim);

    // flipped weights: wsm[i*5+j] = kernel[c, 0, 4-i, 4-j]
    if (tid < 25) wsm[tid] = kern[c * 25 + (24 - tid)];

    // Cooperative tile load: sm[r][q] = x[gy0-2+r][gx0-2+q], -inf out of range.
    #pragma unroll
    for (int base = 0; base < SW * SW; base += 256) {
        int idx = base + tid;
        if (idx < SW * SW) {
            int r = idx / SW;
            int q = idx - r * SW;
            int gy  = gy0 + r - HALO;
            int gxx = gx0 + q - HALO;
            float v = -CUDART_INF_F;
            if ((unsigned)gy < (unsigned)Hdim && (unsigned)gxx < (unsigned)Wdim)
                v = xp[gy * Wdim + gxx];
            sm[idx] = v;
        }
    }
    __syncthreads();

    // Weights to registers (broadcast LDS).
    float w[25];
    #pragma unroll
    for (int i = 0; i < 25; i++) w[i] = wsm[i];

    // Thread layout: tx in 0..7 (4-wide column group), ty in 0..31 (row).
    const int tx = tid & 7;
    const int ty = tid >> 3;

    // Outputs: row gy0+ty, cols gx0 + 4*tx + {0..3}.
    // Needs sm rows ty..ty+4, cols 4*tx .. 4*tx+7 (halo shift already in layout).
    const float* smb = sm + ty * SW + 4 * tx;  // 16B-aligned

    float acc[4];

    #pragma unroll
    for (int r = 0; r < 5; r++) {
        const float4 lo = *reinterpret_cast<const float4*>(smb + r * SW);
        const float4 hi = *reinterpret_cast<const float4*>(smb + r * SW + 4);
        float xv[8] = {lo.x, lo.y, lo.z, lo.w, hi.x, hi.y, hi.z, hi.w};

        if (r == 0) {
            // init from tap j=0
            #pragma unroll
            for (int t = 0; t < 4; t++) acc[t] = xv[t] + w[0];
            #pragma unroll
            for (int j = 1; j < 5; j++) {
                #pragma unroll
                for (int t = 0; t < 4; t++)
                    acc[t] = fmaxf(acc[t], xv[t + j] + w[j]);
            }
        } else {
            #pragma unroll
            for (int j = 0; j < 5; j++) {
                #pragma unroll
                for (int t = 0; t < 4; t++)
                    acc[t] = fmaxf(acc[t], xv[t + j] + w[r * 5 + j]);
            }
        }
    }

    float* __restrict__ op = out + (size_t)bc * (Hdim * Wdim)
                           + (gy0 + ty) * Wdim + gx0 + 4 * tx;
    float4 res = make_float4(acc[0], acc[1], acc[2], acc[3]);
    *reinterpret_cast<float4*>(op) = res;
}

extern "C" void kernel_launch(void* const* d_in, const int* in_sizes, int n_in,
                              void* d_out, int out_size) {
    const float* x    = (const float*)d_in[0];
    const float* kern = (const float*)d_in[1];
    float* out = (float*)d_out;

    dim3 grid(Wdim / TILE, Hdim / TILE, Bdim * Cdim);  // (7, 7, 256)
    tropical_conv_kernel<<<grid, 256>>>(x, kern, out);
}

// round 4
// speedup vs baseline: 1.1087x; 1.0471x over previous
#include <cuda_runtime.h>
#include <math_constants.h>

// Tropical (max-plus) depthwise 5x5 conv, stride=1, pad=2, dil=1.
// x: (8,32,224,224) f32, kernel: (32,1,5,5) f32, out same shape as x.
// out[b,c,y,x] = max_{i,j} x[b,c, y+i-2, x+j-2] + kernel[c,0,4-i,4-j]
//
// R3: issue/alu-bound. 8 outputs/thread (2 rows x 4 cols), float2 tile fill
// with incremental indexing (no div), tile 32x56 / 224 threads.

#define TW 32
#define TH 56
#define SW 36   // TW + 4 halo
#define SH 60   // TH + 4 halo

static constexpr int Hdim = 224;
static constexpr int Wdim = 224;

__global__ __launch_bounds__(224)
void tropical_conv_kernel(const float* __restrict__ x,
                          const float* __restrict__ kern,
                          float* __restrict__ out) {
    __shared__ __align__(16) float sm[SH * SW];
    __shared__ float wsm[25];

    const int tid = threadIdx.x;
    const int bc  = blockIdx.z;          // b*32 + c
    const int c   = bc & 31;
    const int gx0 = blockIdx.x * TW;
    const int gy0 = blockIdx.y * TH;

    const float* __restrict__ xp = x + (size_t)bc * (Hdim * Wdim);

    // flipped weights: wsm[i*5+j] = kernel[c, 0, 4-i, 4-j]
    if (tid < 25) wsm[tid] = kern[c * 25 + (24 - tid)];

    // Tile fill: SH rows x 18 float2 columns = 1080 pairs, 5 iters/thread.
    // Pairs are always fully inside or fully outside the image (gx0, W even),
    // so a single predicate per pair suffices; outside -> -inf.
    {
        int r = tid / 18;            // compile-time magic div, once
        int p = tid - r * 18;
        #pragma unroll
        for (int it = 0; it < 5; it++) {
            if (it < 4 || r < SH) {  // iters 0..3 always in range (tid<224)
                int gy  = gy0 + r - 2;
                int gxs = gx0 + 2 * p - 2;
                float2 v = make_float2(-CUDART_INF_F, -CUDART_INF_F);
                if ((unsigned)gy < (unsigned)Hdim && (unsigned)gxs < (unsigned)Wdim)
                    v = *reinterpret_cast<const float2*>(xp + gy * Wdim + gxs);
                *reinterpret_cast<float2*>(sm + r * SW + 2 * p) = v;
            }
            // advance by 224 pairs: 224 = 12*18 + 8
            r += 12; p += 8;
            if (p >= 18) { p -= 18; r += 1; }
        }
    }
    __syncthreads();

    // Weights to registers (broadcast LDS, conflict-free).
    float w[25];
    #pragma unroll
    for (int i = 0; i < 25; i++) w[i] = wsm[i];

    // Thread layout: tx 0..7 (4-wide col group), ty 0..27 (2 output rows each).
    // Warp phases (lanes 0-7 etc.) share ty -> LDS.128 conflict-free.
    const int tx = tid & 7;
    const int ty = tid >> 3;
    const float* smb = sm + (2 * ty) * SW + 4 * tx;   // 16B-aligned

    float accA[4], accB[4];

    #pragma unroll
    for (int r = 0; r < 6; r++) {
        const float4 lo = *reinterpret_cast<const float4*>(smb + r * SW);
        const float4 hi = *reinterpret_cast<const float4*>(smb + r * SW + 4);
        float xv[8] = {lo.x, lo.y, lo.z, lo.w, hi.x, hi.y, hi.z, hi.w};

        // Output row A (gy0 + 2ty): weight row = r, valid r in [0,4]
        if (r == 0) {
            #pragma unroll
            for (int t = 0; t < 4; t++) accA[t] = xv[t] + w[0];
            #pragma unroll
            for (int j = 1; j < 5; j++)
                #pragma unroll
                for (int t = 0; t < 4; t++)
                    accA[t] = fmaxf(accA[t], xv[t + j] + w[j]);
        } else if (r < 5) {
            #pragma unroll
            for (int j = 0; j < 5; j++)
                #pragma unroll
                for (int t = 0; t < 4; t++)
                    accA[t] = fmaxf(accA[t], xv[t + j] + w[r * 5 + j]);
        }

        // Output row B (gy0 + 2ty + 1): weight row = r-1, valid r in [1,5]
        if (r == 1) {
            #pragma unroll
            for (int t = 0; t < 4; t++) accB[t] = xv[t] + w[0];
            #pragma unroll
            for (int j = 1; j < 5; j++)
                #pragma unroll
                for (int t = 0; t < 4; t++)
                    accB[t] = fmaxf(accB[t], xv[t + j] + w[j]);
        } else if (r >= 2) {
            #pragma unroll
            for (int j = 0; j < 5; j++)
                #pragma unroll
                for (int t = 0; t < 4; t++)
                    accB[t] = fmaxf(accB[t], xv[t + j] + w[(r - 1) * 5 + j]);
        }
    }

    float* __restrict__ op = out + (size_t)bc * (Hdim * Wdim)
                           + (gy0 + 2 * ty) * Wdim + gx0 + 4 * tx;
    *reinterpret_cast<float4*>(op)        = make_float4(accA[0], accA[1], accA[2], accA[3]);
    *reinterpret_cast<float4*>(op + Wdim) = make_float4(accB[0], accB[1], accB[2], accB[3]);
}

extern "C" void kernel_launch(void* const* d_in, const int* in_sizes, int n_in,
                              void* d_out, int out_size) {
    const float* x    = (const float*)d_in[0];
    const float* kern = (const float*)d_in[1];
    float* out = (float*)d_out;

    dim3 grid(Wdim / TW, Hdim / TH, 8 * 32);  // (7, 4, 256)
    tropical_conv_kernel<<<grid, 224>>>(x, kern, out);
}

// round 6
// speedup vs baseline: 1.1730x; 1.0580x over previous
#include <cuda_runtime.h>
#include <math_constants.h>

// Tropical (max-plus) depthwise 5x5 conv, stride=1, pad=2, dil=1.
// x: (8,32,224,224) f32, kernel: (32,1,5,5) f32, out same shape as x.
// out[b,c,y,x] = max_{i,j} x[b,c, y+i-2, x+j-2] + kernel[c,0,4-i,4-j]
//
// R5: weights moved to __constant__ (block-uniform index -> LDCU/UR operands,
// frees ~25 GPRs), __launch_bounds__(224,9) pins occupancy at 63/64 warps.

#define TW 32
#define TH 56
#define SW 36   // TW + 4 halo
#define SH 60   // TH + 4 halo

static constexpr int Hdim = 224;
static constexpr int Wdim = 224;

__constant__ float cw[32 * 25];   // raw (unflipped) kernel, copied from d_in[1]

// flipped weight (i,j) for channel base: kernel[c,0,4-i,4-j] = cw[base + 24 - (5i+j)]
#define WGT(i, j) cw[wbase + (24 - ((i) * 5 + (j)))]

__global__ __launch_bounds__(224, 9)
void tropical_conv_kernel(const float* __restrict__ x,
                          float* __restrict__ out) {
    __shared__ __align__(16) float sm[SH * SW];

    const int tid = threadIdx.x;
    const int bc  = blockIdx.z;          // b*32 + c
    const int wbase = (bc & 31) * 25;    // uniform
    const int gx0 = blockIdx.x * TW;
    const int gy0 = blockIdx.y * TH;

    const float* __restrict__ xp = x + (size_t)bc * (Hdim * Wdim);

    // Tile fill: SH rows x 18 float2 columns = 1080 pairs, 5 iters/thread.
    // Pairs are fully inside or fully outside the image (gx0, W even).
    {
        int r = tid / 18;
        int p = tid - r * 18;
        #pragma unroll
        for (int it = 0; it < 5; it++) {
            if (it < 4 || r < SH) {
                int gy  = gy0 + r - 2;
                int gxs = gx0 + 2 * p - 2;
                float2 v = make_float2(-CUDART_INF_F, -CUDART_INF_F);
                if ((unsigned)gy < (unsigned)Hdim && (unsigned)gxs < (unsigned)Wdim)
                    v = *reinterpret_cast<const float2*>(xp + gy * Wdim + gxs);
                *reinterpret_cast<float2*>(sm + r * SW + 2 * p) = v;
            }
            r += 12; p += 8;
            if (p >= 18) { p -= 18; r += 1; }
        }
    }
    __syncthreads();

    // Thread layout: tx 0..7 (4-wide col group), ty 0..27 (2 output rows).
    const int tx = tid & 7;
    const int ty = tid >> 3;
    const float* smb = sm + (2 * ty) * SW + 4 * tx;   // 16B-aligned

    float accA[4], accB[4];

    #pragma unroll
    for (int r = 0; r < 6; r++) {
        const float4 lo = *reinterpret_cast<const float4*>(smb + r * SW);
        const float4 hi = *reinterpret_cast<const float4*>(smb + r * SW + 4);
        float xv[8] = {lo.x, lo.y, lo.z, lo.w, hi.x, hi.y, hi.z, hi.w};

        // Output row A (gy0 + 2ty): weight row i = r, valid r in [0,4]
        if (r == 0) {
            #pragma unroll
            for (int t = 0; t < 4; t++) accA[t] = xv[t] + WGT(0, 0);
            #pragma unroll
            for (int j = 1; j < 5; j++)
                #pragma unroll
                for (int t = 0; t < 4; t++)
                    accA[t] = fmaxf(accA[t], xv[t + j] + WGT(0, j));
        } else if (r < 5) {
            #pragma unroll
            for (int j = 0; j < 5; j++)
                #pragma unroll
                for (int t = 0; t < 4; t++)
                    accA[t] = fmaxf(accA[t], xv[t + j] + WGT(r, j));
        }

        // Output row B (gy0 + 2ty + 1): weight row i = r-1, valid r in [1,5]
        if (r == 1) {
            #pragma unroll
            for (int t = 0; t < 4; t++) accB[t] = xv[t] + WGT(0, 0);
            #pragma unroll
            for (int j = 1; j < 5; j++)
                #pragma unroll
                for (int t = 0; t < 4; t++)
                    accB[t] = fmaxf(accB[t], xv[t + j] + WGT(0, j));
        } else if (r >= 2) {
            #pragma unroll
            for (int j = 0; j < 5; j++)
                #pragma unroll
                for (int t = 0; t < 4; t++)
                    accB[t] = fmaxf(accB[t], xv[t + j] + WGT(r - 1, j));
        }
    }

    float* __restrict__ op = out + (size_t)bc * (Hdim * Wdim)
                           + (gy0 + 2 * ty) * Wdim + gx0 + 4 * tx;
    *reinterpret_cast<float4*>(op)        = make_float4(accA[0], accA[1], accA[2], accA[3]);
    *reinterpret_cast<float4*>(op + Wdim) = make_float4(accB[0], accB[1], accB[2], accB[3]);
}

extern "C" void kernel_launch(void* const* d_in, const int* in_sizes, int n_in,
                              void* d_out, int out_size) {
    const float* x    = (const float*)d_in[0];
    float* out = (float*)d_out;

    // Stage weights into constant memory (device-to-device, graph-capturable
    // memcpy node; no allocation).
    cudaMemcpyToSymbolAsync(cw, d_in[1], 32 * 25 * sizeof(float), 0,
                            cudaMemcpyDeviceToDevice, 0);

    dim3 grid(Wdim / TW, Hdim / TH, 8 * 32);  // (7, 4, 256)
    tropical_conv_kernel<<<grid, 224>>>(x, out);
}